// round 1
// baseline (speedup 1.0000x reference)
#include <cuda_runtime.h>
#include <cuda_bf16.h>
#include <cstddef>

// Problem constants (fixed by the dataset)
#define Bn   8
#define Qn   900
#define En   256
#define NHn  8
#define HDn  32
#define NLn  4
#define NPn  4
#define Sn   19560
#define BQn  (Bn * Qn)          // 7200
#define Mv   (Bn * Sn)          // 156480

// Scratch (static device globals — no allocations allowed)
__device__ float g_v[(size_t)Bn * Sn * En];      // projected values [B,S,E]
__device__ float g_off[(size_t)BQn * 256];       // sampling offsets  [BQ, NH*NL*NP*2]
__device__ float g_logits[(size_t)BQn * 128];    // attn logits       [BQ, NH*NL*NP]
__device__ float g_mid[(size_t)BQn * En];        // sampled output    [BQ, E]

// ---------------------------------------------------------------------------
// Generic fp32 SGEMM: C[M,N] = A[M,K] @ B[K,N] + bias[N] (+ resid[M,N])
// BM=128, BN=128, BK=16, 256 threads, 8x8 per-thread tile.
// Requires N % 128 == 0 and K % 16 == 0 (true here: N in {128,256}, K=256).
// ---------------------------------------------------------------------------
#define BM 128
#define BN 128
#define BK 16
#define TM 8
#define TN 8

__global__ __launch_bounds__(256, 2)
void sgemm_bias(const float* __restrict__ A, const float* __restrict__ Bw,
                const float* __restrict__ bias, const float* __restrict__ resid,
                float* __restrict__ C, int M, int N, int K)
{
    __shared__ float As[BK][BM];
    __shared__ float Bs[BK][BN];

    const int row0 = blockIdx.y * BM;
    const int col0 = blockIdx.x * BN;
    const int tid  = threadIdx.x;
    const int tx   = tid % 16;   // n-direction
    const int ty   = tid / 16;   // m-direction

    float acc[TM][TN];
#pragma unroll
    for (int i = 0; i < TM; i++)
#pragma unroll
        for (int j = 0; j < TN; j++) acc[i][j] = 0.0f;

    // A tile loads: 128x16 floats, 2 float4 per thread
    const int a_row = tid >> 2;          // 0..63
    const int a_col = (tid & 3) * 4;     // 0,4,8,12
    // B tile loads: 16x128 floats, 2 float4 per thread
    const int b_row = tid >> 5;          // 0..7
    const int b_col = (tid & 31) * 4;    // 0..124

    for (int k0 = 0; k0 < K; k0 += BK) {
#pragma unroll
        for (int i = 0; i < 2; i++) {
            int r = row0 + a_row + i * 64;
            float4 va = make_float4(0.f, 0.f, 0.f, 0.f);
            if (r < M) va = *(const float4*)(A + (size_t)r * K + k0 + a_col);
            As[a_col + 0][a_row + i * 64] = va.x;
            As[a_col + 1][a_row + i * 64] = va.y;
            As[a_col + 2][a_row + i * 64] = va.z;
            As[a_col + 3][a_row + i * 64] = va.w;
        }
#pragma unroll
        for (int i = 0; i < 2; i++) {
            int r = b_row + i * 8;
            float4 vb = *(const float4*)(Bw + (size_t)(k0 + r) * N + col0 + b_col);
            *(float4*)&Bs[r][b_col] = vb;
        }
        __syncthreads();

#pragma unroll
        for (int kk = 0; kk < BK; kk++) {
            float ar[TM], br[TN];
#pragma unroll
            for (int i = 0; i < TM; i++) ar[i] = As[kk][ty * TM + i];
#pragma unroll
            for (int j = 0; j < TN; j++) br[j] = Bs[kk][tx * TN + j];
#pragma unroll
            for (int i = 0; i < TM; i++)
#pragma unroll
                for (int j = 0; j < TN; j++) acc[i][j] += ar[i] * br[j];
        }
        __syncthreads();
    }

#pragma unroll
    for (int i = 0; i < TM; i++) {
        int r = row0 + ty * TM + i;
        if (r >= M) continue;
#pragma unroll
        for (int j = 0; j < TN; j += 4) {
            int c = col0 + tx * TN + j;
            float4 o;
            o.x = acc[i][j + 0] + bias[c + 0];
            o.y = acc[i][j + 1] + bias[c + 1];
            o.z = acc[i][j + 2] + bias[c + 2];
            o.w = acc[i][j + 3] + bias[c + 3];
            if (resid) {
                const float4 rr = *(const float4*)(resid + (size_t)r * N + c);
                o.x += rr.x; o.y += rr.y; o.z += rr.z; o.w += rr.w;
            }
            *(float4*)(C + (size_t)r * N + c) = o;
        }
    }
}

// ---------------------------------------------------------------------------
// Fused softmax + multi-scale deformable bilinear sampling.
// One block per (b,q) row, 256 threads; thread t owns output channel t
// (head h = t/32, channel d = t%32).
// ---------------------------------------------------------------------------
__global__ __launch_bounds__(256, 4)
void msda_sample(const float* __restrict__ off, const float* __restrict__ logits,
                 const float* __restrict__ ref, const float* __restrict__ v,
                 float* __restrict__ mid)
{
    const int lvlH[NLn]     = {92, 46, 23, 12};
    const int lvlW[NLn]     = {160, 80, 40, 20};
    const int lvlStart[NLn] = {0, 14720, 18400, 19320};

    const int row = blockIdx.x;      // b*Q + q
    const int b   = row / Qn;
    const int t   = threadIdx.x;

    __shared__ float s_loc[256];     // pixel-space sampling locations (pre -0.5)
    __shared__ float s_lg[128];      // logits
    __shared__ float s_w[128];       // softmax weights

    // sampling locations: index t = ((h*NL + l)*NP + p)*2 + c
    {
        const int c = t & 1;
        const int l = (t >> 3) & 3;
        const float dim = (c == 0) ? (float)lvlW[l] : (float)lvlH[l];
        const float r = ref[((size_t)row * NLn + l) * 2 + c];
        s_loc[t] = r * dim - 0.5f + off[(size_t)row * 256 + t];
    }
    if (t < 128) s_lg[t] = logits[(size_t)row * 128 + t];
    __syncthreads();

    // per-head softmax over 16 (l,p) entries
    if (t < 128) {
        const int h = t >> 4;
        float m = -1e30f;
#pragma unroll
        for (int i = 0; i < 16; i++) m = fmaxf(m, s_lg[h * 16 + i]);
        float sum = 0.0f;
#pragma unroll
        for (int i = 0; i < 16; i++) sum += __expf(s_lg[h * 16 + i] - m);
        s_w[t] = __expf(s_lg[t] - m) / sum;
    }
    __syncthreads();

    const int h = t >> 5;
    const int d = t & 31;
    const float* vb = v + (size_t)b * Sn * En + h * HDn + d;

    float acc = 0.0f;
#pragma unroll
    for (int l = 0; l < NLn; l++) {
        const int Hl = lvlH[l], Wl = lvlW[l];
        const float* vl = vb + (size_t)lvlStart[l] * En;
#pragma unroll
        for (int p = 0; p < NPn; p++) {
            const int idx = (h * NLn + l) * NPn + p;
            const float x = s_loc[idx * 2 + 0];
            const float y = s_loc[idx * 2 + 1];
            const float w = s_w[idx];
            const float xf = floorf(x), yf = floorf(y);
            const float wx = x - xf, wy = y - yf;
            const int x0 = (int)xf, y0 = (int)yf;

            float c00, c01, c10, c11;
            {
                int yy = y0, xx = x0;
                bool val = (yy >= 0) & (yy < Hl) & (xx >= 0) & (xx < Wl);
                int yc = min(max(yy, 0), Hl - 1), xc = min(max(xx, 0), Wl - 1);
                float g = vl[(size_t)(yc * Wl + xc) * En];
                c00 = val ? g : 0.0f;
            }
            {
                int yy = y0, xx = x0 + 1;
                bool val = (yy >= 0) & (yy < Hl) & (xx >= 0) & (xx < Wl);
                int yc = min(max(yy, 0), Hl - 1), xc = min(max(xx, 0), Wl - 1);
                float g = vl[(size_t)(yc * Wl + xc) * En];
                c01 = val ? g : 0.0f;
            }
            {
                int yy = y0 + 1, xx = x0;
                bool val = (yy >= 0) & (yy < Hl) & (xx >= 0) & (xx < Wl);
                int yc = min(max(yy, 0), Hl - 1), xc = min(max(xx, 0), Wl - 1);
                float g = vl[(size_t)(yc * Wl + xc) * En];
                c10 = val ? g : 0.0f;
            }
            {
                int yy = y0 + 1, xx = x0 + 1;
                bool val = (yy >= 0) & (yy < Hl) & (xx >= 0) & (xx < Wl);
                int yc = min(max(yy, 0), Hl - 1), xc = min(max(xx, 0), Wl - 1);
                float g = vl[(size_t)(yc * Wl + xc) * En];
                c11 = val ? g : 0.0f;
            }

            const float top = c00 + wx * (c01 - c00);
            const float bot = c10 + wx * (c11 - c10);
            acc += w * (top + wy * (bot - top));
        }
    }

    mid[(size_t)row * En + t] = acc;
}

// ---------------------------------------------------------------------------
// Launch: inputs in metadata order:
// 0 query [B,Q,E]            1 value [B,S,E]        2 reference_points [B,Q,NL,2]
// 3 spatial_shapes [NL,2]    4 W_off [E,256]        5 b_off [256]
// 6 W_attn [E,128]           7 b_attn [128]         8 W_v [E,E]
// 9 b_v [E]                 10 W_out [E,E]         11 b_out [E]
// ---------------------------------------------------------------------------
extern "C" void kernel_launch(void* const* d_in, const int* in_sizes, int n_in,
                              void* d_out, int out_size)
{
    const float* query  = (const float*)d_in[0];
    const float* value  = (const float*)d_in[1];
    const float* refpts = (const float*)d_in[2];
    const float* W_off  = (const float*)d_in[4];
    const float* b_off  = (const float*)d_in[5];
    const float* W_attn = (const float*)d_in[6];
    const float* b_attn = (const float*)d_in[7];
    const float* W_v    = (const float*)d_in[8];
    const float* b_v    = (const float*)d_in[9];
    const float* W_out  = (const float*)d_in[10];
    const float* b_out  = (const float*)d_in[11];
    float* out = (float*)d_out;

    void *pv, *poff, *plg, *pmid;
    cudaGetSymbolAddress(&pv, g_v);
    cudaGetSymbolAddress(&poff, g_off);
    cudaGetSymbolAddress(&plg, g_logits);
    cudaGetSymbolAddress(&pmid, g_mid);
    float* v_s   = (float*)pv;
    float* off_s = (float*)poff;
    float* lg_s  = (float*)plg;
    float* mid_s = (float*)pmid;

    // 1) value projection: [156480,256] @ [256,256]
    {
        dim3 grid(En / BN, (Mv + BM - 1) / BM);
        sgemm_bias<<<grid, 256>>>(value, W_v, b_v, nullptr, v_s, Mv, En, En);
    }
    // 2) sampling-offset projection: [7200,256] @ [256,256]
    {
        dim3 grid(256 / BN, (BQn + BM - 1) / BM);
        sgemm_bias<<<grid, 256>>>(query, W_off, b_off, nullptr, off_s, BQn, 256, En);
    }
    // 3) attention-logit projection: [7200,256] @ [256,128]
    {
        dim3 grid(128 / BN, (BQn + BM - 1) / BM);
        sgemm_bias<<<grid, 256>>>(query, W_attn, b_attn, nullptr, lg_s, BQn, 128, En);
    }
    // 4) softmax + deformable bilinear sampling
    msda_sample<<<BQn, 256>>>(off_s, lg_s, refpts, v_s, mid_s);

    // 5) output projection + residual: [7200,256] @ [256,256] + query
    {
        dim3 grid(En / BN, (BQn + BM - 1) / BM);
        sgemm_bias<<<grid, 256>>>(mid_s, W_out, b_out, query, out, BQn, En, En);
    }
}

// round 3
// speedup vs baseline: 2.0330x; 2.0330x over previous
#include <cuda_runtime.h>
#include <cuda_bf16.h>
#include <cstdint>
#include <cstddef>

// Problem constants
#define Bn   8
#define Qn   900
#define En   256
#define NHn  8
#define HDn  32
#define NLn  4
#define NPn  4
#define Sn   19560
#define BQn  (Bn * Qn)          // 7200
#define Mv   (Bn * Sn)          // 156480

// Scratch (static device globals)
__device__ float g_v[(size_t)Bn * Sn * En];      // projected values [B,S,E]
__device__ float g_off[(size_t)BQn * 256];
__device__ float g_logits[(size_t)BQn * 128];
__device__ float g_mid[(size_t)BQn * En];

// ---------------------------------------------------------------------------
// tf32 tensor-core GEMM via mma.sync (sm_80+ PTX, works on plain sm_103).
// C[M,N] = A[M,K] @ B[K,N] + bias[N].  B consumed row-major [K][N] directly.
// CTA 128x128, K-chunk 32. 8 warps (2m x 4n), warp tile 64x32.
// ---------------------------------------------------------------------------
__device__ __forceinline__ uint32_t f2tf32(float f) {
    uint32_t r;
    asm("cvt.rna.tf32.f32 %0, %1;" : "=r"(r) : "f"(f));
    return r;
}

__device__ __forceinline__ void mma_tf32(float* c, const uint32_t* a, const uint32_t* b) {
    asm volatile(
        "mma.sync.aligned.m16n8k8.row.col.f32.tf32.tf32.f32 "
        "{%0,%1,%2,%3}, {%4,%5,%6,%7}, {%8,%9}, {%0,%1,%2,%3};"
        : "+f"(c[0]), "+f"(c[1]), "+f"(c[2]), "+f"(c[3])
        : "r"(a[0]), "r"(a[1]), "r"(a[2]), "r"(a[3]), "r"(b[0]), "r"(b[1]));
}

__global__ __launch_bounds__(256, 2)
void gemm_tf32(const float* __restrict__ A, const float* __restrict__ Bw,
               const float* __restrict__ bias, float* __restrict__ C,
               int M, int N, int K)
{
    __shared__ uint32_t As[128][36];   // [m][k], pad->conflict-free frag reads
    __shared__ uint32_t Bs[32][132];   // [k][n]

    const int tid  = threadIdx.x;
    const int lane = tid & 31;
    const int wid  = tid >> 5;
    const int wm   = wid >> 2;         // 0..1
    const int wn   = wid & 3;          // 0..3
    const int g    = lane >> 2;        // 0..7
    const int tg   = lane & 3;         // 0..3
    const int m0   = blockIdx.y * 128;
    const int n0   = blockIdx.x * 128;

    float c[4][4][4];
#pragma unroll
    for (int i = 0; i < 4; i++)
#pragma unroll
        for (int j = 0; j < 4; j++)
#pragma unroll
            for (int r = 0; r < 4; r++) c[i][j][r] = 0.0f;

    const int a_kq = tid & 7;          // float4 column in K-chunk
    const int a_m  = tid >> 3;         // 0..31
    const int b_n4 = tid & 31;         // float4 column in N
    const int b_k  = tid >> 5;         // 0..7

    for (int k0 = 0; k0 < K; k0 += 32) {
        // A tile 128x32 (coalesced: 4 rows x 128B per warp)
#pragma unroll
        for (int i = 0; i < 4; i++) {
            int m = a_m + 32 * i;
            float4 v = make_float4(0.f, 0.f, 0.f, 0.f);
            if (m0 + m < M) v = *(const float4*)(A + (size_t)(m0 + m) * K + k0 + a_kq * 4);
            uint4 t;
            t.x = f2tf32(v.x); t.y = f2tf32(v.y); t.z = f2tf32(v.z); t.w = f2tf32(v.w);
            *(uint4*)&As[m][a_kq * 4] = t;
        }
        // B tile 32x128 (coalesced: 512B contiguous per warp)
#pragma unroll
        for (int i = 0; i < 4; i++) {
            int k = b_k + 8 * i;
            float4 v = *(const float4*)(Bw + (size_t)(k0 + k) * N + n0 + b_n4 * 4);
            uint4 t;
            t.x = f2tf32(v.x); t.y = f2tf32(v.y); t.z = f2tf32(v.z); t.w = f2tf32(v.w);
            *(uint4*)&Bs[k][b_n4 * 4] = t;
        }
        __syncthreads();

#pragma unroll
        for (int kk = 0; kk < 4; kk++) {
            uint32_t a[4][4], b[4][2];
#pragma unroll
            for (int mf = 0; mf < 4; mf++) {
                int m = wm * 64 + mf * 16 + g;
                a[mf][0] = As[m][kk * 8 + tg];
                a[mf][1] = As[m + 8][kk * 8 + tg];
                a[mf][2] = As[m][kk * 8 + tg + 4];
                a[mf][3] = As[m + 8][kk * 8 + tg + 4];
            }
#pragma unroll
            for (int nf = 0; nf < 4; nf++) {
                int n = wn * 32 + nf * 8 + g;
                b[nf][0] = Bs[kk * 8 + tg][n];
                b[nf][1] = Bs[kk * 8 + tg + 4][n];
            }
#pragma unroll
            for (int mf = 0; mf < 4; mf++)
#pragma unroll
                for (int nf = 0; nf < 4; nf++)
                    mma_tf32(c[mf][nf], a[mf], b[nf]);
        }
        __syncthreads();
    }

    // Epilogue: direct float2 stores (+bias)
#pragma unroll
    for (int mf = 0; mf < 4; mf++) {
        const int r0 = m0 + wm * 64 + mf * 16 + g;
        const int r1 = r0 + 8;
#pragma unroll
        for (int nf = 0; nf < 4; nf++) {
            const int cb = n0 + wn * 32 + nf * 8 + 2 * tg;
            const float bx = bias[cb], by = bias[cb + 1];
            if (r0 < M) {
                float2 o = make_float2(c[mf][nf][0] + bx, c[mf][nf][1] + by);
                *(float2*)(C + (size_t)r0 * N + cb) = o;
            }
            if (r1 < M) {
                float2 o = make_float2(c[mf][nf][2] + bx, c[mf][nf][3] + by);
                *(float2*)(C + (size_t)r1 * N + cb) = o;
            }
        }
    }
}

// ---------------------------------------------------------------------------
// fp32 SGEMM (small BQ projections + output proj, kept for accuracy)
// ---------------------------------------------------------------------------
#define BM 128
#define BN 128
#define BK 16
#define TM 8
#define TN 8

__global__ __launch_bounds__(256, 2)
void sgemm_bias(const float* __restrict__ A, const float* __restrict__ Bw,
                const float* __restrict__ bias, const float* __restrict__ resid,
                float* __restrict__ C, int M, int N, int K)
{
    __shared__ float As[BK][BM];
    __shared__ float Bs[BK][BN];

    const int row0 = blockIdx.y * BM;
    const int col0 = blockIdx.x * BN;
    const int tid  = threadIdx.x;
    const int tx   = tid % 16;
    const int ty   = tid / 16;

    float acc[TM][TN];
#pragma unroll
    for (int i = 0; i < TM; i++)
#pragma unroll
        for (int j = 0; j < TN; j++) acc[i][j] = 0.0f;

    const int a_row = tid >> 2;
    const int a_col = (tid & 3) * 4;
    const int b_row = tid >> 5;
    const int b_col = (tid & 31) * 4;

    for (int k0 = 0; k0 < K; k0 += BK) {
#pragma unroll
        for (int i = 0; i < 2; i++) {
            int r = row0 + a_row + i * 64;
            float4 va = make_float4(0.f, 0.f, 0.f, 0.f);
            if (r < M) va = *(const float4*)(A + (size_t)r * K + k0 + a_col);
            As[a_col + 0][a_row + i * 64] = va.x;
            As[a_col + 1][a_row + i * 64] = va.y;
            As[a_col + 2][a_row + i * 64] = va.z;
            As[a_col + 3][a_row + i * 64] = va.w;
        }
#pragma unroll
        for (int i = 0; i < 2; i++) {
            int r = b_row + i * 8;
            float4 vb = *(const float4*)(Bw + (size_t)(k0 + r) * N + col0 + b_col);
            *(float4*)&Bs[r][b_col] = vb;
        }
        __syncthreads();

#pragma unroll
        for (int kk = 0; kk < BK; kk++) {
            float ar[TM], br[TN];
#pragma unroll
            for (int i = 0; i < TM; i++) ar[i] = As[kk][ty * TM + i];
#pragma unroll
            for (int j = 0; j < TN; j++) br[j] = Bs[kk][tx * TN + j];
#pragma unroll
            for (int i = 0; i < TM; i++)
#pragma unroll
                for (int j = 0; j < TN; j++) acc[i][j] += ar[i] * br[j];
        }
        __syncthreads();
    }

#pragma unroll
    for (int i = 0; i < TM; i++) {
        int r = row0 + ty * TM + i;
        if (r >= M) continue;
#pragma unroll
        for (int j = 0; j < TN; j += 4) {
            int c = col0 + tx * TN + j;
            float4 o;
            o.x = acc[i][j + 0] + bias[c + 0];
            o.y = acc[i][j + 1] + bias[c + 1];
            o.z = acc[i][j + 2] + bias[c + 2];
            o.w = acc[i][j + 3] + bias[c + 3];
            if (resid) {
                const float4 rr = *(const float4*)(resid + (size_t)r * N + c);
                o.x += rr.x; o.y += rr.y; o.z += rr.z; o.w += rr.w;
            }
            *(float4*)(C + (size_t)r * N + c) = o;
        }
    }
}

// ---------------------------------------------------------------------------
// Fused softmax + multi-scale deformable bilinear sampling
// ---------------------------------------------------------------------------
__global__ __launch_bounds__(256, 4)
void msda_sample(const float* __restrict__ off, const float* __restrict__ logits,
                 const float* __restrict__ ref, const float* __restrict__ v,
                 float* __restrict__ mid)
{
    const int lvlH[NLn]     = {92, 46, 23, 12};
    const int lvlW[NLn]     = {160, 80, 40, 20};
    const int lvlStart[NLn] = {0, 14720, 18400, 19320};

    const int row = blockIdx.x;
    const int b   = row / Qn;
    const int t   = threadIdx.x;

    __shared__ float s_loc[256];
    __shared__ float s_lg[128];
    __shared__ float s_w[128];

    {
        const int c = t & 1;
        const int l = (t >> 3) & 3;
        const float dim = (c == 0) ? (float)lvlW[l] : (float)lvlH[l];
        const float r = ref[((size_t)row * NLn + l) * 2 + c];
        s_loc[t] = r * dim - 0.5f + off[(size_t)row * 256 + t];
    }
    if (t < 128) s_lg[t] = logits[(size_t)row * 128 + t];
    __syncthreads();

    if (t < 128) {
        const int h = t >> 4;
        float m = -1e30f;
#pragma unroll
        for (int i = 0; i < 16; i++) m = fmaxf(m, s_lg[h * 16 + i]);
        float sum = 0.0f;
#pragma unroll
        for (int i = 0; i < 16; i++) sum += __expf(s_lg[h * 16 + i] - m);
        s_w[t] = __expf(s_lg[t] - m) / sum;
    }
    __syncthreads();

    const int h = t >> 5;
    const int d = t & 31;
    const float* vb = v + (size_t)b * Sn * En + h * HDn + d;

    float acc = 0.0f;
#pragma unroll
    for (int l = 0; l < NLn; l++) {
        const int Hl = lvlH[l], Wl = lvlW[l];
        const float* vl = vb + (size_t)lvlStart[l] * En;
#pragma unroll
        for (int p = 0; p < NPn; p++) {
            const int idx = (h * NLn + l) * NPn + p;
            const float x = s_loc[idx * 2 + 0];
            const float y = s_loc[idx * 2 + 1];
            const float w = s_w[idx];
            const float xf = floorf(x), yf = floorf(y);
            const float wx = x - xf, wy = y - yf;
            const int x0 = (int)xf, y0 = (int)yf;

            float c00, c01, c10, c11;
            {
                int yy = y0, xx = x0;
                bool val = (yy >= 0) & (yy < Hl) & (xx >= 0) & (xx < Wl);
                int yc = min(max(yy, 0), Hl - 1), xc = min(max(xx, 0), Wl - 1);
                float g = vl[(size_t)(yc * Wl + xc) * En];
                c00 = val ? g : 0.0f;
            }
            {
                int yy = y0, xx = x0 + 1;
                bool val = (yy >= 0) & (yy < Hl) & (xx >= 0) & (xx < Wl);
                int yc = min(max(yy, 0), Hl - 1), xc = min(max(xx, 0), Wl - 1);
                float g = vl[(size_t)(yc * Wl + xc) * En];
                c01 = val ? g : 0.0f;
            }
            {
                int yy = y0 + 1, xx = x0;
                bool val = (yy >= 0) & (yy < Hl) & (xx >= 0) & (xx < Wl);
                int yc = min(max(yy, 0), Hl - 1), xc = min(max(xx, 0), Wl - 1);
                float g = vl[(size_t)(yc * Wl + xc) * En];
                c10 = val ? g : 0.0f;
            }
            {
                int yy = y0 + 1, xx = x0 + 1;
                bool val = (yy >= 0) & (yy < Hl) & (xx >= 0) & (xx < Wl);
                int yc = min(max(yy, 0), Hl - 1), xc = min(max(xx, 0), Wl - 1);
                float g = vl[(size_t)(yc * Wl + xc) * En];
                c11 = val ? g : 0.0f;
            }

            const float top = c00 + wx * (c01 - c00);
            const float bot = c10 + wx * (c11 - c10);
            acc += w * (top + wy * (bot - top));
        }
    }

    mid[(size_t)row * En + t] = acc;
}

// ---------------------------------------------------------------------------
extern "C" void kernel_launch(void* const* d_in, const int* in_sizes, int n_in,
                              void* d_out, int out_size)
{
    const float* query  = (const float*)d_in[0];
    const float* value  = (const float*)d_in[1];
    const float* refpts = (const float*)d_in[2];
    const float* W_off  = (const float*)d_in[4];
    const float* b_off  = (const float*)d_in[5];
    const float* W_attn = (const float*)d_in[6];
    const float* b_attn = (const float*)d_in[7];
    const float* W_v    = (const float*)d_in[8];
    const float* b_v    = (const float*)d_in[9];
    const float* W_out  = (const float*)d_in[10];
    const float* b_out  = (const float*)d_in[11];
    float* out = (float*)d_out;

    void *pv, *poff, *plg, *pmid;
    cudaGetSymbolAddress(&pv, g_v);
    cudaGetSymbolAddress(&poff, g_off);
    cudaGetSymbolAddress(&plg, g_logits);
    cudaGetSymbolAddress(&pmid, g_mid);
    float* v_s   = (float*)pv;
    float* off_s = (float*)poff;
    float* lg_s  = (float*)plg;
    float* mid_s = (float*)pmid;

    // 1) value projection on tf32 tensor cores: [156480,256] @ [256,256]
    {
        dim3 grid(En / 128, (Mv + 127) / 128);
        gemm_tf32<<<grid, 256>>>(value, W_v, b_v, v_s, Mv, En, En);
    }
    // 2) sampling-offset projection: [7200,256] @ [256,256]
    {
        dim3 grid(256 / BN, (BQn + BM - 1) / BM);
        sgemm_bias<<<grid, 256>>>(query, W_off, b_off, nullptr, off_s, BQn, 256, En);
    }
    // 3) attention-logit projection: [7200,256] @ [256,128]
    {
        dim3 grid(128 / BN, (BQn + BM - 1) / BM);
        sgemm_bias<<<grid, 256>>>(query, W_attn, b_attn, nullptr, lg_s, BQn, 128, En);
    }
    // 4) softmax + deformable bilinear sampling
    msda_sample<<<BQn, 256>>>(off_s, lg_s, refpts, v_s, mid_s);
    // 5) output projection + residual
    {
        dim3 grid(En / BN, (BQn + BM - 1) / BM);
        sgemm_bias<<<grid, 256>>>(mid_s, W_out, b_out, query, out, BQn, En, En);
    }
}

// round 5
// speedup vs baseline: 2.1916x; 1.0780x over previous
#include <cuda_runtime.h>
#include <cuda_bf16.h>
#include <cstdint>
#include <cstddef>

// Problem constants
#define Bn   8
#define Qn   900
#define En   256
#define NHn  8
#define HDn  32
#define NLn  4
#define NPn  4
#define Sn   19560
#define BQn  (Bn * Qn)          // 7200
#define Mv   (Bn * Sn)          // 156480

// Scratch (static device globals)
__device__ float g_v[(size_t)Bn * Sn * En];      // projected values [B,S,E]
__device__ float g_off[(size_t)BQn * 256];
__device__ float g_logits[(size_t)BQn * 128];
__device__ float g_mid[(size_t)BQn * En];

// ---------------------------------------------------------------------------
// tf32 tensor-core GEMM via mma.sync — round-3 verbatim (known passing).
// C[M,N] = A[M,K] @ B[K,N] + bias[N].  CTA 128x128, K-chunk 32.
// ---------------------------------------------------------------------------
__device__ __forceinline__ uint32_t f2tf32(float f) {
    uint32_t r;
    asm("cvt.rna.tf32.f32 %0, %1;" : "=r"(r) : "f"(f));
    return r;
}

__device__ __forceinline__ void mma_tf32(float* c, const uint32_t* a, const uint32_t* b) {
    asm volatile(
        "mma.sync.aligned.m16n8k8.row.col.f32.tf32.tf32.f32 "
        "{%0,%1,%2,%3}, {%4,%5,%6,%7}, {%8,%9}, {%0,%1,%2,%3};"
        : "+f"(c[0]), "+f"(c[1]), "+f"(c[2]), "+f"(c[3])
        : "r"(a[0]), "r"(a[1]), "r"(a[2]), "r"(a[3]), "r"(b[0]), "r"(b[1]));
}

__global__ __launch_bounds__(256, 2)
void gemm_tf32(const float* __restrict__ A, const float* __restrict__ Bw,
               const float* __restrict__ bias, float* __restrict__ C,
               int M, int N, int K)
{
    __shared__ uint32_t As[128][36];   // [m][k]
    __shared__ uint32_t Bs[32][132];   // [k][n]

    const int tid  = threadIdx.x;
    const int lane = tid & 31;
    const int wid  = tid >> 5;
    const int wm   = wid >> 2;
    const int wn   = wid & 3;
    const int g    = lane >> 2;
    const int tg   = lane & 3;
    const int m0   = blockIdx.y * 128;
    const int n0   = blockIdx.x * 128;

    float c[4][4][4];
#pragma unroll
    for (int i = 0; i < 4; i++)
#pragma unroll
        for (int j = 0; j < 4; j++)
#pragma unroll
            for (int r = 0; r < 4; r++) c[i][j][r] = 0.0f;

    const int a_kq = tid & 7;
    const int a_m  = tid >> 3;
    const int b_n4 = tid & 31;
    const int b_k  = tid >> 5;

    for (int k0 = 0; k0 < K; k0 += 32) {
#pragma unroll
        for (int i = 0; i < 4; i++) {
            int m = a_m + 32 * i;
            float4 v = make_float4(0.f, 0.f, 0.f, 0.f);
            if (m0 + m < M) v = *(const float4*)(A + (size_t)(m0 + m) * K + k0 + a_kq * 4);
            uint4 t;
            t.x = f2tf32(v.x); t.y = f2tf32(v.y); t.z = f2tf32(v.z); t.w = f2tf32(v.w);
            *(uint4*)&As[m][a_kq * 4] = t;
        }
#pragma unroll
        for (int i = 0; i < 4; i++) {
            int k = b_k + 8 * i;
            float4 v = *(const float4*)(Bw + (size_t)(k0 + k) * N + n0 + b_n4 * 4);
            uint4 t;
            t.x = f2tf32(v.x); t.y = f2tf32(v.y); t.z = f2tf32(v.z); t.w = f2tf32(v.w);
            *(uint4*)&Bs[k][b_n4 * 4] = t;
        }
        __syncthreads();

#pragma unroll
        for (int kk = 0; kk < 4; kk++) {
            uint32_t a[4][4], b[4][2];
#pragma unroll
            for (int mf = 0; mf < 4; mf++) {
                int m = wm * 64 + mf * 16 + g;
                a[mf][0] = As[m][kk * 8 + tg];
                a[mf][1] = As[m + 8][kk * 8 + tg];
                a[mf][2] = As[m][kk * 8 + tg + 4];
                a[mf][3] = As[m + 8][kk * 8 + tg + 4];
            }
#pragma unroll
            for (int nf = 0; nf < 4; nf++) {
                int n = wn * 32 + nf * 8 + g;
                b[nf][0] = Bs[kk * 8 + tg][n];
                b[nf][1] = Bs[kk * 8 + tg + 4][n];
            }
#pragma unroll
            for (int mf = 0; mf < 4; mf++)
#pragma unroll
                for (int nf = 0; nf < 4; nf++)
                    mma_tf32(c[mf][nf], a[mf], b[nf]);
        }
        __syncthreads();
    }

#pragma unroll
    for (int mf = 0; mf < 4; mf++) {
        const int r0 = m0 + wm * 64 + mf * 16 + g;
        const int r1 = r0 + 8;
#pragma unroll
        for (int nf = 0; nf < 4; nf++) {
            const int cb = n0 + wn * 32 + nf * 8 + 2 * tg;
            const float bx = bias[cb], by = bias[cb + 1];
            if (r0 < M) {
                float2 o = make_float2(c[mf][nf][0] + bx, c[mf][nf][1] + by);
                *(float2*)(C + (size_t)r0 * N + cb) = o;
            }
            if (r1 < M) {
                float2 o = make_float2(c[mf][nf][2] + bx, c[mf][nf][3] + by);
                *(float2*)(C + (size_t)r1 * N + cb) = o;
            }
        }
    }
}

// ---------------------------------------------------------------------------
// fp32 SGEMM — round-3 verbatim (known passing).
// ---------------------------------------------------------------------------
#define BM 128
#define BN 128
#define BK 16
#define TM 8
#define TN 8

__global__ __launch_bounds__(256, 2)
void sgemm_bias(const float* __restrict__ A, const float* __restrict__ Bw,
                const float* __restrict__ bias, const float* __restrict__ resid,
                float* __restrict__ C, int M, int N, int K)
{
    __shared__ float As[BK][BM];
    __shared__ float Bs[BK][BN];

    const int row0 = blockIdx.y * BM;
    const int col0 = blockIdx.x * BN;
    const int tid  = threadIdx.x;
    const int tx   = tid % 16;
    const int ty   = tid / 16;

    float acc[TM][TN];
#pragma unroll
    for (int i = 0; i < TM; i++)
#pragma unroll
        for (int j = 0; j < TN; j++) acc[i][j] = 0.0f;

    const int a_row = tid >> 2;
    const int a_col = (tid & 3) * 4;
    const int b_row = tid >> 5;
    const int b_col = (tid & 31) * 4;

    for (int k0 = 0; k0 < K; k0 += BK) {
#pragma unroll
        for (int i = 0; i < 2; i++) {
            int r = row0 + a_row + i * 64;
            float4 va = make_float4(0.f, 0.f, 0.f, 0.f);
            if (r < M) va = *(const float4*)(A + (size_t)r * K + k0 + a_col);
            As[a_col + 0][a_row + i * 64] = va.x;
            As[a_col + 1][a_row + i * 64] = va.y;
            As[a_col + 2][a_row + i * 64] = va.z;
            As[a_col + 3][a_row + i * 64] = va.w;
        }
#pragma unroll
        for (int i = 0; i < 2; i++) {
            int r = b_row + i * 8;
            float4 vb = *(const float4*)(Bw + (size_t)(k0 + r) * N + col0 + b_col);
            *(float4*)&Bs[r][b_col] = vb;
        }
        __syncthreads();

#pragma unroll
        for (int kk = 0; kk < BK; kk++) {
            float ar[TM], br[TN];
#pragma unroll
            for (int i = 0; i < TM; i++) ar[i] = As[kk][ty * TM + i];
#pragma unroll
            for (int j = 0; j < TN; j++) br[j] = Bs[kk][tx * TN + j];
#pragma unroll
            for (int i = 0; i < TM; i++)
#pragma unroll
                for (int j = 0; j < TN; j++) acc[i][j] += ar[i] * br[j];
        }
        __syncthreads();
    }

#pragma unroll
    for (int i = 0; i < TM; i++) {
        int r = row0 + ty * TM + i;
        if (r >= M) continue;
#pragma unroll
        for (int j = 0; j < TN; j += 4) {
            int c = col0 + tx * TN + j;
            float4 o;
            o.x = acc[i][j + 0] + bias[c + 0];
            o.y = acc[i][j + 1] + bias[c + 1];
            o.z = acc[i][j + 2] + bias[c + 2];
            o.w = acc[i][j + 3] + bias[c + 3];
            if (resid) {
                const float4 rr = *(const float4*)(resid + (size_t)r * N + c);
                o.x += rr.x; o.y += rr.y; o.z += rr.z; o.w += rr.w;
            }
            *(float4*)(C + (size_t)r * N + c) = o;
        }
    }
}

// ---------------------------------------------------------------------------
// Fused softmax + deformable sampling — NEW precompute structure (the single
// experimental change this round). Threads 0..127 precompute per-sample
// clamped gather indices + attn-premultiplied bilinear corner weights; the
// main loop is pure gather + FMA.
// ---------------------------------------------------------------------------
__global__ __launch_bounds__(256, 4)
void msda_sample(const float* __restrict__ off, const float* __restrict__ logits,
                 const float* __restrict__ ref, const float* __restrict__ v,
                 float* __restrict__ mid)
{
    const int lvlH[NLn]     = {92, 46, 23, 12};
    const int lvlW[NLn]     = {160, 80, 40, 20};
    const int lvlStart[NLn] = {0, 14720, 18400, 19320};

    const int row = blockIdx.x;
    const int b   = row / Qn;
    const int t   = threadIdx.x;

    __shared__ float s_loc[256];
    __shared__ float s_lg[128];
    __shared__ int4   s_idx[128];   // 4 corner indices per sample (clamped, level-global)
    __shared__ float4 s_wgt[128];   // 4 premultiplied weights per sample

    // pixel-space sampling locations: col t = ((h*4+l)*4+p)*2+c
    {
        const int c = t & 1;
        const int l = (t >> 3) & 3;
        const float dim = (c == 0) ? (float)lvlW[l] : (float)lvlH[l];
        const float r = ref[((size_t)row * NLn + l) * 2 + c];
        s_loc[t] = r * dim - 0.5f + off[(size_t)row * 256 + t];
    }
    if (t < 128) s_lg[t] = logits[(size_t)row * 128 + t];
    __syncthreads();

    if (t < 128) {
        // softmax over 16 (l,p) per head
        const int h = t >> 4;
        float m = -1e30f;
#pragma unroll
        for (int i = 0; i < 16; i++) m = fmaxf(m, s_lg[h * 16 + i]);
        float sum = 0.0f;
#pragma unroll
        for (int i = 0; i < 16; i++) sum += __expf(s_lg[h * 16 + i] - m);
        const float w = __expf(s_lg[t] - m) / sum;

        // sample id t = h*16 + l*4 + p; its loc cols are t*2, t*2+1
        const int l = (t >> 2) & 3;
        const int Hl = lvlH[l], Wl = lvlW[l], base = lvlStart[l];
        const float x = s_loc[t * 2 + 0];
        const float y = s_loc[t * 2 + 1];
        const float xf = floorf(x), yf = floorf(y);
        const float wx = x - xf, wy = y - yf;
        const int x0 = (int)xf, y0 = (int)yf, x1 = x0 + 1, y1 = y0 + 1;

        const bool vx0 = (x0 >= 0) & (x0 < Wl), vx1 = (x1 >= 0) & (x1 < Wl);
        const bool vy0 = (y0 >= 0) & (y0 < Hl), vy1 = (y1 >= 0) & (y1 < Hl);
        const int xc0 = min(max(x0, 0), Wl - 1), xc1 = min(max(x1, 0), Wl - 1);
        const int yc0 = min(max(y0, 0), Hl - 1), yc1 = min(max(y1, 0), Hl - 1);

        int4 id;
        id.x = base + yc0 * Wl + xc0;
        id.y = base + yc0 * Wl + xc1;
        id.z = base + yc1 * Wl + xc0;
        id.w = base + yc1 * Wl + xc1;
        s_idx[t] = id;
        float4 ww;
        ww.x = (vy0 & vx0) ? w * (1.f - wy) * (1.f - wx) : 0.f;
        ww.y = (vy0 & vx1) ? w * (1.f - wy) * wx : 0.f;
        ww.z = (vy1 & vx0) ? w * wy * (1.f - wx) : 0.f;
        ww.w = (vy1 & vx1) ? w * wy * wx : 0.f;
        s_wgt[t] = ww;
    }
    __syncthreads();

    const int h = t >> 5;
    const int d = t & 31;
    const float* __restrict__ vb = v + (size_t)b * Sn * En + h * HDn + d;

    float acc = 0.0f;
#pragma unroll
    for (int s = 0; s < 16; s++) {
        const int si = h * 16 + s;
        const int4   id = s_idx[si];
        const float4 ww = s_wgt[si];
        acc += ww.x * vb[(size_t)id.x * En];
        acc += ww.y * vb[(size_t)id.y * En];
        acc += ww.z * vb[(size_t)id.z * En];
        acc += ww.w * vb[(size_t)id.w * En];
    }

    mid[(size_t)row * En + t] = acc;
}

// ---------------------------------------------------------------------------
extern "C" void kernel_launch(void* const* d_in, const int* in_sizes, int n_in,
                              void* d_out, int out_size)
{
    const float* query  = (const float*)d_in[0];
    const float* value  = (const float*)d_in[1];
    const float* refpts = (const float*)d_in[2];
    const float* W_off  = (const float*)d_in[4];
    const float* b_off  = (const float*)d_in[5];
    const float* W_attn = (const float*)d_in[6];
    const float* b_attn = (const float*)d_in[7];
    const float* W_v    = (const float*)d_in[8];
    const float* b_v    = (const float*)d_in[9];
    const float* W_out  = (const float*)d_in[10];
    const float* b_out  = (const float*)d_in[11];
    float* out = (float*)d_out;

    void *pv, *poff, *plg, *pmid;
    cudaGetSymbolAddress(&pv, g_v);
    cudaGetSymbolAddress(&poff, g_off);
    cudaGetSymbolAddress(&plg, g_logits);
    cudaGetSymbolAddress(&pmid, g_mid);
    float* v_s   = (float*)pv;
    float* off_s = (float*)poff;
    float* lg_s  = (float*)plg;
    float* mid_s = (float*)pmid;

    // 1) value projection on tf32 tensor cores: [156480,256] @ [256,256]
    {
        dim3 grid(En / 128, (Mv + 127) / 128);
        gemm_tf32<<<grid, 256>>>(value, W_v, b_v, v_s, Mv, En, En);
    }
    // 2) sampling-offset projection: [7200,256] @ [256,256]  (fp32)
    {
        dim3 grid(256 / BN, (BQn + BM - 1) / BM);
        sgemm_bias<<<grid, 256>>>(query, W_off, b_off, nullptr, off_s, BQn, 256, En);
    }
    // 3) attention-logit projection: [7200,256] @ [256,128]  (fp32)
    {
        dim3 grid(128 / BN, (BQn + BM - 1) / BM);
        sgemm_bias<<<grid, 256>>>(query, W_attn, b_attn, nullptr, lg_s, BQn, 128, En);
    }
    // 4) softmax + deformable bilinear sampling (restructured)
    msda_sample<<<BQn, 256>>>(off_s, lg_s, refpts, v_s, mid_s);
    // 5) output projection + residual (fp32)
    {
        dim3 grid(En / BN, (BQn + BM - 1) / BM);
        sgemm_bias<<<grid, 256>>>(mid_s, W_out, b_out, query, out, BQn, En, En);
    }
}

// round 6
// speedup vs baseline: 2.7891x; 1.2727x over previous
#include <cuda_runtime.h>
#include <cuda_bf16.h>
#include <cstdint>
#include <cstddef>

// Problem constants
#define Bn   8
#define Qn   900
#define En   256
#define NHn  8
#define HDn  32
#define NLn  4
#define NPn  4
#define Sn   19560
#define BQn  (Bn * Qn)          // 7200
#define Mv   (Bn * Sn)          // 156480

// Scratch (static device globals)
__device__ float g_v[(size_t)Bn * Sn * En];      // projected values [B,S,E]
__device__ float g_off[(size_t)BQn * 256];
__device__ float g_logits[(size_t)BQn * 128];
__device__ float g_mid[(size_t)BQn * En];

// ---------------------------------------------------------------------------
// tf32 tensor-core GEMM via mma.sync — round-3 proven core, plus optional
// fp32 residual add in the epilogue.
// C[M,N] = A[M,K] @ B[K,N] + bias[N] (+ resid[M,N]).
// CTA 128x128, K-chunk 32, 8 warps (2m x 4n), warp tile 64x32.
// Requires K % 32 == 0, N % 128 == 0 (N in {128, 256} here).
// ---------------------------------------------------------------------------
__device__ __forceinline__ uint32_t f2tf32(float f) {
    uint32_t r;
    asm("cvt.rna.tf32.f32 %0, %1;" : "=r"(r) : "f"(f));
    return r;
}

__device__ __forceinline__ void mma_tf32(float* c, const uint32_t* a, const uint32_t* b) {
    asm volatile(
        "mma.sync.aligned.m16n8k8.row.col.f32.tf32.tf32.f32 "
        "{%0,%1,%2,%3}, {%4,%5,%6,%7}, {%8,%9}, {%0,%1,%2,%3};"
        : "+f"(c[0]), "+f"(c[1]), "+f"(c[2]), "+f"(c[3])
        : "r"(a[0]), "r"(a[1]), "r"(a[2]), "r"(a[3]), "r"(b[0]), "r"(b[1]));
}

__global__ __launch_bounds__(256, 2)
void gemm_tf32(const float* __restrict__ A, const float* __restrict__ Bw,
               const float* __restrict__ bias, const float* __restrict__ resid,
               float* __restrict__ C, int M, int N, int K)
{
    __shared__ uint32_t As[128][36];   // [m][k]
    __shared__ uint32_t Bs[32][132];   // [k][n]

    const int tid  = threadIdx.x;
    const int lane = tid & 31;
    const int wid  = tid >> 5;
    const int wm   = wid >> 2;
    const int wn   = wid & 3;
    const int g    = lane >> 2;
    const int tg   = lane & 3;
    const int m0   = blockIdx.y * 128;
    const int n0   = blockIdx.x * 128;

    float c[4][4][4];
#pragma unroll
    for (int i = 0; i < 4; i++)
#pragma unroll
        for (int j = 0; j < 4; j++)
#pragma unroll
            for (int r = 0; r < 4; r++) c[i][j][r] = 0.0f;

    const int a_kq = tid & 7;
    const int a_m  = tid >> 3;
    const int b_n4 = tid & 31;
    const int b_k  = tid >> 5;

    for (int k0 = 0; k0 < K; k0 += 32) {
#pragma unroll
        for (int i = 0; i < 4; i++) {
            int m = a_m + 32 * i;
            float4 v = make_float4(0.f, 0.f, 0.f, 0.f);
            if (m0 + m < M) v = *(const float4*)(A + (size_t)(m0 + m) * K + k0 + a_kq * 4);
            uint4 t;
            t.x = f2tf32(v.x); t.y = f2tf32(v.y); t.z = f2tf32(v.z); t.w = f2tf32(v.w);
            *(uint4*)&As[m][a_kq * 4] = t;
        }
#pragma unroll
        for (int i = 0; i < 4; i++) {
            int k = b_k + 8 * i;
            float4 v = *(const float4*)(Bw + (size_t)(k0 + k) * N + n0 + b_n4 * 4);
            uint4 t;
            t.x = f2tf32(v.x); t.y = f2tf32(v.y); t.z = f2tf32(v.z); t.w = f2tf32(v.w);
            *(uint4*)&Bs[k][b_n4 * 4] = t;
        }
        __syncthreads();

#pragma unroll
        for (int kk = 0; kk < 4; kk++) {
            uint32_t a[4][4], b[4][2];
#pragma unroll
            for (int mf = 0; mf < 4; mf++) {
                int m = wm * 64 + mf * 16 + g;
                a[mf][0] = As[m][kk * 8 + tg];
                a[mf][1] = As[m + 8][kk * 8 + tg];
                a[mf][2] = As[m][kk * 8 + tg + 4];
                a[mf][3] = As[m + 8][kk * 8 + tg + 4];
            }
#pragma unroll
            for (int nf = 0; nf < 4; nf++) {
                int n = wn * 32 + nf * 8 + g;
                b[nf][0] = Bs[kk * 8 + tg][n];
                b[nf][1] = Bs[kk * 8 + tg + 4][n];
            }
#pragma unroll
            for (int mf = 0; mf < 4; mf++)
#pragma unroll
                for (int nf = 0; nf < 4; nf++)
                    mma_tf32(c[mf][nf], a[mf], b[nf]);
        }
        __syncthreads();
    }

#pragma unroll
    for (int mf = 0; mf < 4; mf++) {
        const int r0 = m0 + wm * 64 + mf * 16 + g;
        const int r1 = r0 + 8;
#pragma unroll
        for (int nf = 0; nf < 4; nf++) {
            const int cb = n0 + wn * 32 + nf * 8 + 2 * tg;
            const float bx = bias[cb], by = bias[cb + 1];
            if (r0 < M) {
                float2 o = make_float2(c[mf][nf][0] + bx, c[mf][nf][1] + by);
                if (resid) {
                    const float2 rr = *(const float2*)(resid + (size_t)r0 * N + cb);
                    o.x += rr.x; o.y += rr.y;
                }
                *(float2*)(C + (size_t)r0 * N + cb) = o;
            }
            if (r1 < M) {
                float2 o = make_float2(c[mf][nf][2] + bx, c[mf][nf][3] + by);
                if (resid) {
                    const float2 rr = *(const float2*)(resid + (size_t)r1 * N + cb);
                    o.x += rr.x; o.y += rr.y;
                }
                *(float2*)(C + (size_t)r1 * N + cb) = o;
            }
        }
    }
}

// ---------------------------------------------------------------------------
// Fused softmax + deformable sampling — round-5 proven.
// ---------------------------------------------------------------------------
__global__ __launch_bounds__(256, 4)
void msda_sample(const float* __restrict__ off, const float* __restrict__ logits,
                 const float* __restrict__ ref, const float* __restrict__ v,
                 float* __restrict__ mid)
{
    const int lvlH[NLn]     = {92, 46, 23, 12};
    const int lvlW[NLn]     = {160, 80, 40, 20};
    const int lvlStart[NLn] = {0, 14720, 18400, 19320};

    const int row = blockIdx.x;
    const int b   = row / Qn;
    const int t   = threadIdx.x;

    __shared__ float s_loc[256];
    __shared__ float s_lg[128];
    __shared__ int4   s_idx[128];
    __shared__ float4 s_wgt[128];

    {
        const int c = t & 1;
        const int l = (t >> 3) & 3;
        const float dim = (c == 0) ? (float)lvlW[l] : (float)lvlH[l];
        const float r = ref[((size_t)row * NLn + l) * 2 + c];
        s_loc[t] = r * dim - 0.5f + off[(size_t)row * 256 + t];
    }
    if (t < 128) s_lg[t] = logits[(size_t)row * 128 + t];
    __syncthreads();

    if (t < 128) {
        const int h = t >> 4;
        float m = -1e30f;
#pragma unroll
        for (int i = 0; i < 16; i++) m = fmaxf(m, s_lg[h * 16 + i]);
        float sum = 0.0f;
#pragma unroll
        for (int i = 0; i < 16; i++) sum += __expf(s_lg[h * 16 + i] - m);
        const float w = __expf(s_lg[t] - m) / sum;

        const int l = (t >> 2) & 3;
        const int Hl = lvlH[l], Wl = lvlW[l], base = lvlStart[l];
        const float x = s_loc[t * 2 + 0];
        const float y = s_loc[t * 2 + 1];
        const float xf = floorf(x), yf = floorf(y);
        const float wx = x - xf, wy = y - yf;
        const int x0 = (int)xf, y0 = (int)yf, x1 = x0 + 1, y1 = y0 + 1;

        const bool vx0 = (x0 >= 0) & (x0 < Wl), vx1 = (x1 >= 0) & (x1 < Wl);
        const bool vy0 = (y0 >= 0) & (y0 < Hl), vy1 = (y1 >= 0) & (y1 < Hl);
        const int xc0 = min(max(x0, 0), Wl - 1), xc1 = min(max(x1, 0), Wl - 1);
        const int yc0 = min(max(y0, 0), Hl - 1), yc1 = min(max(y1, 0), Hl - 1);

        int4 id;
        id.x = base + yc0 * Wl + xc0;
        id.y = base + yc0 * Wl + xc1;
        id.z = base + yc1 * Wl + xc0;
        id.w = base + yc1 * Wl + xc1;
        s_idx[t] = id;
        float4 ww;
        ww.x = (vy0 & vx0) ? w * (1.f - wy) * (1.f - wx) : 0.f;
        ww.y = (vy0 & vx1) ? w * (1.f - wy) * wx : 0.f;
        ww.z = (vy1 & vx0) ? w * wy * (1.f - wx) : 0.f;
        ww.w = (vy1 & vx1) ? w * wy * wx : 0.f;
        s_wgt[t] = ww;
    }
    __syncthreads();

    const int h = t >> 5;
    const int d = t & 31;
    const float* __restrict__ vb = v + (size_t)b * Sn * En + h * HDn + d;

    float acc = 0.0f;
#pragma unroll
    for (int s = 0; s < 16; s++) {
        const int si = h * 16 + s;
        const int4   id = s_idx[si];
        const float4 ww = s_wgt[si];
        acc += ww.x * vb[(size_t)id.x * En];
        acc += ww.y * vb[(size_t)id.y * En];
        acc += ww.z * vb[(size_t)id.z * En];
        acc += ww.w * vb[(size_t)id.w * En];
    }

    mid[(size_t)row * En + t] = acc;
}

// ---------------------------------------------------------------------------
extern "C" void kernel_launch(void* const* d_in, const int* in_sizes, int n_in,
                              void* d_out, int out_size)
{
    const float* query  = (const float*)d_in[0];
    const float* value  = (const float*)d_in[1];
    const float* refpts = (const float*)d_in[2];
    const float* W_off  = (const float*)d_in[4];
    const float* b_off  = (const float*)d_in[5];
    const float* W_attn = (const float*)d_in[6];
    const float* b_attn = (const float*)d_in[7];
    const float* W_v    = (const float*)d_in[8];
    const float* b_v    = (const float*)d_in[9];
    const float* W_out  = (const float*)d_in[10];
    const float* b_out  = (const float*)d_in[11];
    float* out = (float*)d_out;

    void *pv, *poff, *plg, *pmid;
    cudaGetSymbolAddress(&pv, g_v);
    cudaGetSymbolAddress(&poff, g_off);
    cudaGetSymbolAddress(&plg, g_logits);
    cudaGetSymbolAddress(&pmid, g_mid);
    float* v_s   = (float*)pv;
    float* off_s = (float*)poff;
    float* lg_s  = (float*)plg;
    float* mid_s = (float*)pmid;

    // 1) value projection: [156480,256] @ [256,256]  (tf32)
    {
        dim3 grid(En / 128, (Mv + 127) / 128);
        gemm_tf32<<<grid, 256>>>(value, W_v, b_v, nullptr, v_s, Mv, En, En);
    }
    // 2) sampling-offset projection: [7200,256] @ [256,256]  (tf32)
    {
        dim3 grid(256 / 128, (BQn + 127) / 128);
        gemm_tf32<<<grid, 256>>>(query, W_off, b_off, nullptr, off_s, BQn, 256, En);
    }
    // 3) attention-logit projection: [7200,256] @ [256,128]  (tf32)
    {
        dim3 grid(128 / 128, (BQn + 127) / 128);
        gemm_tf32<<<grid, 256>>>(query, W_attn, b_attn, nullptr, lg_s, BQn, 128, En);
    }
    // 4) softmax + deformable bilinear sampling
    msda_sample<<<BQn, 256>>>(off_s, lg_s, refpts, v_s, mid_s);
    // 5) output projection + residual: [7200,256] @ [256,256] + query  (tf32)
    {
        dim3 grid(En / 128, (BQn + 127) / 128);
        gemm_tf32<<<grid, 256>>>(mid_s, W_out, b_out, query, out, BQn, En, En);
    }
}